// round 15
// baseline (speedup 1.0000x reference)
#include <cuda_runtime.h>

// Local cost volume (SpatialCorrelationSampler, kernel_size=1, patch 9x9):
// out[b, p, y, x] = sum_c t1[b,c,y,x] * t2[b,c,y+di,x+dj],  p=(di+4)*9+(dj+4)
// t1,t2 [4,128,128,256] f32 -> out [4,81,128,256] f32.
//
// Pure-LDG variant: NO shared memory, NO barriers, NO cp.async. CTA = 96
// threads = 3 warps (one x-tile of 128 px, three di rows; di-group in the
// fastest grid bits for L2 reuse). Per warp-channel: 1 t1 LDG.128 + 3
// overlapping t2 LDG.128 (L1 serves the 3x window overlap). 4 px/lane,
// packed fma.rn.f32x2, unroll-2 channel loop for MLP. 8 CTAs/SM.

#define CH 128
#define HH 128
#define WW 256
#define MD 4
#define DD 9
#define NDI 3
#define XT 128
#define HW (HH*WW)
#define NTHREADS 96

typedef unsigned long long u64;

__device__ __forceinline__ u64 pk(float lo, float hi) {
    u64 r; asm("mov.b64 %0, {%1,%2};" : "=l"(r) : "f"(lo), "f"(hi)); return r;
}
__device__ __forceinline__ void fma2(u64 &d, u64 a, u64 b) {
    asm("fma.rn.f32x2 %0, %1, %2, %0;" : "+l"(d) : "l"(a), "l"(b));
}
__device__ __forceinline__ float2 upk(u64 v) {
    float lo, hi; asm("mov.b64 {%0,%1}, %2;" : "=f"(lo), "=f"(hi) : "l"(v));
    return make_float2(lo, hi);
}

__global__ __launch_bounds__(NTHREADS, 8)
void corr_volume_kernel(const float* __restrict__ t1,
                        const float* __restrict__ t2,
                        float* __restrict__ out)
{
    const int tid   = threadIdx.x;
    const int wid   = tid >> 5;             // 0..2 within CTA
    const int lane  = tid & 31;

    // bid = (((batch*HH + y)*2 + xt)*3 + dig)  -- dig fastest (L2 reuse)
    const int blk  = blockIdx.x;            // 0..3071
    const int dig  = blk - (blk / 3) * 3;   // di group 0..2
    const int rest = blk / 3;
    const int xt    = rest & 1;
    const int y     = (rest >> 1) & (HH - 1);
    const int batch = rest >> 8;
    const int x0    = xt * XT;
    const int di    = dig * NDI + wid;      // 0..8

    const int gy = y + di - MD;
    const bool vrow = (unsigned)gy < (unsigned)HH;     // warp-uniform

    u64 acc[DD][2];
    #pragma unroll
    for (int d = 0; d < DD; d++) { acc[d][0] = 0ull; acc[d][1] = 0ull; }

    const int xl = lane * 4;

    if (vrow) {
        // window floats f0..f11 = gx in [X-4, X+8), X = x0+xl (16B aligned)
        const float* wbase = t2 + (size_t)batch * CH * HW + (size_t)gy * WW
                               + (x0 + xl - 4);
        const float* abase = t1 + (size_t)batch * CH * HW + (size_t)y * WW
                               + (x0 + xl);

        // whole-quad invalidity only at the grid edge lanes:
        const bool ok0 = !(xt == 0 && lane == 0);    // v0 = gx[-4..-1]
        const bool ok2 = !(xt == 1 && lane == 31);   // v2 = gx[256..259]
        const float* w0base = ok0 ? wbase     : wbase + 4;   // clamped safe addr
        const float* w2base = ok2 ? wbase + 8 : wbase + 4;

        #pragma unroll 2
        for (int c = 0; c < CH; c++) {
            const size_t co = (size_t)c * HW;
            float4 a  = *(const float4*)(abase + co);
            float4 v0 = *(const float4*)(w0base + co);
            float4 v1 = *(const float4*)(wbase + 4 + co);
            float4 v2 = *(const float4*)(w2base + co);
            if (!ok0) v0 = make_float4(0.f, 0.f, 0.f, 0.f);
            if (!ok2) v2 = make_float4(0.f, 0.f, 0.f, 0.f);

            u64 A0 = pk(a.x, a.y), A1 = pk(a.z, a.w);

            u64 P[6];
            P[0] = pk(v0.x, v0.y); P[1] = pk(v0.z, v0.w);
            P[2] = pk(v1.x, v1.y); P[3] = pk(v1.z, v1.w);
            P[4] = pk(v2.x, v2.y); P[5] = pk(v2.z, v2.w);
            u64 Q[5];
            Q[0] = pk(v0.y, v0.z); Q[1] = pk(v0.w, v1.x);
            Q[2] = pk(v1.y, v1.z); Q[3] = pk(v1.w, v2.x);
            Q[4] = pk(v2.y, v2.z);

            #pragma unroll
            for (int dj = 0; dj < DD; dj++) {
                const int h = dj >> 1;
                if ((dj & 1) == 0) {
                    fma2(acc[dj][0], A0, P[h + 0]);
                    fma2(acc[dj][1], A1, P[h + 1]);
                } else {
                    fma2(acc[dj][0], A0, Q[h + 0]);
                    fma2(acc[dj][1], A1, Q[h + 1]);
                }
            }
        }
    }

    // ---- write out: p = di*9 + dj ----
    size_t obase = (((size_t)batch * 81 + (size_t)di * DD) * HH + y) * WW + x0 + xl;
    #pragma unroll
    for (int dj = 0; dj < DD; dj++) {
        float2 p0 = upk(acc[dj][0]), p1 = upk(acc[dj][1]);
        *(float4*)&out[obase + (size_t)dj * HW] = make_float4(p0.x, p0.y, p1.x, p1.y);
    }
}

extern "C" void kernel_launch(void* const* d_in, const int* in_sizes, int n_in,
                              void* d_out, int out_size)
{
    const float* t1 = (const float*)d_in[0];
    const float* t2 = (const float*)d_in[1];
    float* out = (float*)d_out;
    corr_volume_kernel<<<2 * 4 * HH * (DD / NDI), NTHREADS>>>(t1, t2, out);
}

// round 16
// speedup vs baseline: 1.5544x; 1.5544x over previous
#include <cuda_runtime.h>

// Local cost volume (SpatialCorrelationSampler, kernel_size=1, patch 9x9):
// out[b, p, y, x] = sum_c t1[b,c,y,x] * t2[b,c,y+di,x+dj],  p=(di+4)*9+(dj+4)
// t1,t2 [4,128,128,256] f32 -> out [4,81,128,256] f32.
//
// Y-PAIR kernel: CTA = 160 threads = 5 warps, covering one x-tile (128 px)
// and TWO output rows (y0, y0+1). Warp w owns t2 row r = y0-4 + dig*5 + w
// (dig in {0,1} from the grid). That single t2 row feeds BOTH
// out(y0, di=r-y0+4) and out(y0+1, di=r-y0+3): the t2 window registers and
// odd-pair packs are shared; only the t1 operand and accumulators double.
// Crossbar bytes per output drop ~40% vs the one-y kernel.
// 4 px/lane, packed fma.rn.f32x2, 2-stage cp.async, 3 CTAs/SM.

#define CH 128
#define HH 128
#define WW 256
#define MD 4
#define DD 9
#define CC 4
#define XT 128
#define T2C 136           // 34 granules of 4 floats
#define HW (HH*WW)
#define NW 5              // t2 rows (= warps) per CTA
#define YP 2              // output rows per CTA
#define NTHREADS 160
#define NCHUNK 32
#define STAGES 2

#define T1_STG (CC*YP*XT)       // 1024 floats
#define T2_STG (CC*NW*T2C)      // 2720 floats
#define SMEM_BYTES (STAGES*(T1_STG+T2_STG)*4)   // 29,952 B

typedef unsigned long long u64;

__device__ __forceinline__ u64 pk(float lo, float hi) {
    u64 r; asm("mov.b64 %0, {%1,%2};" : "=l"(r) : "f"(lo), "f"(hi)); return r;
}
__device__ __forceinline__ void fma2(u64 &d, u64 a, u64 b) {
    asm("fma.rn.f32x2 %0, %1, %2, %0;" : "+l"(d) : "l"(a), "l"(b));
}
__device__ __forceinline__ float2 upk(u64 v) {
    float lo, hi; asm("mov.b64 {%0,%1}, %2;" : "=f"(lo), "=f"(hi) : "l"(v));
    return make_float2(lo, hi);
}
__device__ __forceinline__ void cpasync16(unsigned smem_addr, const void* gptr) {
    asm volatile("cp.async.cg.shared.global [%0], [%1], 16;" ::
                 "r"(smem_addr), "l"(gptr));
}

__global__ __launch_bounds__(NTHREADS, 3)
void corr_volume_kernel(const float* __restrict__ t1,
                        const float* __restrict__ t2,
                        float* __restrict__ out)
{
    extern __shared__ float sm[];
    float* s_t1 = sm;                       // [STAGES][CC][YP][XT]
    float* s_t2 = sm + STAGES * T1_STG;     // [STAGES][CC][NW][T2C]

    const int tid   = threadIdx.x;
    const int wid   = tid >> 5;             // 0..4
    const int lane  = tid & 31;

    // bid = (((batch*64 + yp)*2 + xt)*2 + dig)   -- dig fastest
    const int blk   = blockIdx.x;           // 0..1023
    const int dig   = blk & 1;
    const int xt    = (blk >> 1) & 1;
    const int yp    = (blk >> 2) & 63;
    const int batch = blk >> 8;
    const int y0    = yp * YP;
    const int x0    = xt * XT;

    const int r_off = dig * NW + wid;       // 0..9
    const int gy    = y0 - MD + r_off;      // this warp's t2 row
    const bool vrow = (unsigned)gy < (unsigned)HH;     // warp-uniform
    const bool has_a = (r_off <= 8);        // out(y0,   di = r_off)
    const bool has_b = (r_off >= 1);        // out(y0+1, di = r_off-1)

    // halo: smem col j holds gx = x0 + j - 4; valid granules [lo, lo+33),
    // one pad granule per row at hpad.
    const int lo   = (xt == 0) ? 1 : 0;
    const int hpad = (xt == 0) ? 0 : 33;

    // ---- one-time zero of constant pad regions (both stages) ----
    {
        const float4 z = make_float4(0.f, 0.f, 0.f, 0.f);
        #pragma unroll
        for (int st = 0; st < STAGES; st++)
            #pragma unroll
            for (int cc = 0; cc < CC; cc++) {
                float* row = s_t2 + (size_t)st * T2_STG + (cc * NW + wid) * T2C;
                if (vrow) {
                    if (lane == 0) *(float4*)&row[4 * hpad] = z;
                } else {
                    *(float4*)&row[4 * lane] = z;
                    if (lane < 2) *(float4*)&row[4 * (32 + lane)] = z;
                }
            }
    }

    u64 accA[DD][2], accB[DD][2];
    #pragma unroll
    for (int d = 0; d < DD; d++) {
        accA[d][0] = 0ull; accA[d][1] = 0ull;
        accB[d][0] = 0ull; accB[d][1] = 0ull;
    }

    const int xl = lane * 4;

    // ---- t2 fill (per warp, own row): lane -> granule lo+lane, lane0 extra ----
    const unsigned t2b = (unsigned)__cvta_generic_to_shared(s_t2);
    const unsigned t2d1 = t2b + (unsigned)(wid * T2C + 4 * (lo + lane)) * 4;
    const unsigned t2d2 = t2b + (unsigned)(wid * T2C + 4 * (lo + 32)) * 4;
    const float* t2src = t2 + (size_t)batch * CH * HW
                            + (size_t)(vrow ? gy : 0) * WW + (x0 - 4 + 4 * lo);

    // ---- t1 fill: 256 granules (cc 0..3, yy 0..1, col 0..31) ----
    const unsigned t1b = (unsigned)__cvta_generic_to_shared(s_t1);
    const int g1 = tid, g2 = tid + NTHREADS;          // g2 valid if tid < 96
    const int cc1 = g1 >> 6, yy1 = (g1 >> 5) & 1, c1 = g1 & 31;
    const int cc2 = g2 >> 6, yy2 = (g2 >> 5) & 1, c2 = g2 & 31;
    const unsigned t1d1 = t1b + (unsigned)((cc1 * YP + yy1) * XT + 4 * c1) * 4;
    const unsigned t1d2 = t1b + (unsigned)((cc2 * YP + yy2) * XT + 4 * c2) * 4;
    const float* t1base = t1 + (size_t)batch * CH * HW + (size_t)y0 * WW + x0;
    const float* t1s1 = t1base + (size_t)cc1 * HW + (size_t)yy1 * WW + 4 * c1;
    const float* t1s2 = t1base + (size_t)cc2 * HW + (size_t)yy2 * WW + 4 * c2;

    auto issue = [&](int chunk) {
        const int c0 = chunk * CC;
        const unsigned stoff = (chunk & 1) ? 1u : 0u;
        if (vrow) {
            const float* src = t2src + (size_t)c0 * HW;
            const unsigned so = stoff * (T2_STG * 4);
            #pragma unroll
            for (int cc = 0; cc < CC; cc++) {
                const unsigned co = so + (unsigned)(cc * (NW * T2C)) * 4;
                cpasync16(t2d1 + co, src + (size_t)cc * HW + 4 * lane);
                if (lane == 0) cpasync16(t2d2 + co, src + (size_t)cc * HW + 128);
            }
        }
        {
            const unsigned so = stoff * (T1_STG * 4);
            cpasync16(t1d1 + so, t1s1 + (size_t)c0 * HW);
            if (tid < 96) cpasync16(t1d2 + so, t1s2 + (size_t)c0 * HW);
        }
        asm volatile("cp.async.commit_group;");
    };

    issue(0);

    for (int it = 0; it < NCHUNK; it++) {
        const int st = it & 1;
        asm volatile("cp.async.wait_group 0;");
        __syncthreads();               // chunk `it` visible; other stage free
        if (it + 1 < NCHUNK) issue(it + 1);

        const float* b_t1 = s_t1 + (size_t)st * T1_STG;
        const float* b_t2 = s_t2 + (size_t)st * T2_STG;

        #pragma unroll
        for (int cc = 0; cc < CC; cc++) {
            const float* ar = &b_t1[(cc * YP) * XT + xl];
            float4 a0 = *(const float4*)(ar);          // t1 row y0
            float4 a1 = *(const float4*)(ar + XT);     // t1 row y0+1
            u64 A0 = pk(a0.x, a0.y), A1 = pk(a0.z, a0.w);
            u64 B0 = pk(a1.x, a1.y), B1 = pk(a1.z, a1.w);

            const float* tr = &b_t2[(cc * NW + wid) * T2C + xl];
            float4 v0 = *(const float4*)&tr[0];
            float4 v1 = *(const float4*)&tr[4];
            float4 v2 = *(const float4*)&tr[8];

            u64 P[6];
            P[0] = pk(v0.x, v0.y); P[1] = pk(v0.z, v0.w);
            P[2] = pk(v1.x, v1.y); P[3] = pk(v1.z, v1.w);
            P[4] = pk(v2.x, v2.y); P[5] = pk(v2.z, v2.w);
            u64 Q[5];
            Q[0] = pk(v0.y, v0.z); Q[1] = pk(v0.w, v1.x);
            Q[2] = pk(v1.y, v1.z); Q[3] = pk(v1.w, v2.x);
            Q[4] = pk(v2.y, v2.z);

            #pragma unroll
            for (int dj = 0; dj < DD; dj++) {
                const int h = dj >> 1;
                if ((dj & 1) == 0) {
                    fma2(accA[dj][0], A0, P[h + 0]);
                    fma2(accA[dj][1], A1, P[h + 1]);
                    fma2(accB[dj][0], B0, P[h + 0]);
                    fma2(accB[dj][1], B1, P[h + 1]);
                } else {
                    fma2(accA[dj][0], A0, Q[h + 0]);
                    fma2(accA[dj][1], A1, Q[h + 1]);
                    fma2(accB[dj][0], B0, Q[h + 0]);
                    fma2(accB[dj][1], B1, Q[h + 1]);
                }
            }
        }
    }

    // ---- write out ----
    if (has_a) {      // out(y0, di = r_off)
        size_t ob = (((size_t)batch * 81 + (size_t)r_off * DD) * HH + y0) * WW
                  + x0 + xl;
        #pragma unroll
        for (int dj = 0; dj < DD; dj++) {
            float2 p0 = upk(accA[dj][0]), p1 = upk(accA[dj][1]);
            *(float4*)&out[ob + (size_t)dj * HW] =
                make_float4(p0.x, p0.y, p1.x, p1.y);
        }
    }
    if (has_b) {      // out(y0+1, di = r_off-1)
        size_t ob = (((size_t)batch * 81 + (size_t)(r_off - 1) * DD) * HH
                  + (y0 + 1)) * WW + x0 + xl;
        #pragma unroll
        for (int dj = 0; dj < DD; dj++) {
            float2 p0 = upk(accB[dj][0]), p1 = upk(accB[dj][1]);
            *(float4*)&out[ob + (size_t)dj * HW] =
                make_float4(p0.x, p0.y, p1.x, p1.y);
        }
    }
}

extern "C" void kernel_launch(void* const* d_in, const int* in_sizes, int n_in,
                              void* d_out, int out_size)
{
    const float* t1 = (const float*)d_in[0];
    const float* t2 = (const float*)d_in[1];
    float* out = (float*)d_out;
    cudaFuncSetAttribute(corr_volume_kernel,
                         cudaFuncAttributeMaxDynamicSharedMemorySize, SMEM_BYTES);
    corr_volume_kernel<<<4 * (HH / YP) * 2 * 2, NTHREADS, SMEM_BYTES>>>(t1, t2, out);
}